// round 3
// baseline (speedup 1.0000x reference)
#include <cuda_runtime.h>
#include <math.h>

// ---------------------------------------------------------------------------
// Problem constants
// ---------------------------------------------------------------------------
#define B_ 4
#define V_ 8
#define D_ 64
#define N_ 16
#define H_ 32
#define W_ 32
#define HW 1024
#define GROUPS 4
#define EPS 1e-5f

// ---------------------------------------------------------------------------
// Scratch (device globals; no dynamic allocation allowed)
// ---------------------------------------------------------------------------
__device__ float  g_unorm[B_ * D_ * HW];   // group-normed u_t
__device__ float  g_delta[B_ * D_ * HW];   // clipped softplus delta
__device__ float  g_du   [B_ * D_ * HW];   // delta * u_t
__device__ float  g_Bv   [B_ * N_ * HW];   // conv_B(u_norm)
__device__ float  g_Cv   [B_ * N_ * HW];   // conv_C(u_norm)
__device__ float  g_A    [D_ * N_];        // -exp(log_A_real)
__device__ float4 g_wtab [V_ * HW];        // bilinear weights (masked)
__device__ short4 g_itab [V_ * HW];        // padded-smem tap offsets (stride 33)

// ---------------------------------------------------------------------------
// Kernel 0: init  (A matrix + rotation sampling tables)
// ---------------------------------------------------------------------------
__global__ void k_init(const float* __restrict__ log_A_real) {
    int gid = blockIdx.x * blockDim.x + threadIdx.x;
    if (gid < D_ * N_) {
        g_A[gid] = -expf(log_A_real[gid]);
    }
    if (gid < V_ * HW) {
        int v = gid >> 10;
        int p = gid & 1023;
        int h = p >> 5, w = p & 31;
        // double precision, matching numpy/math float64 path then cast to f32
        double a = -(45.0 * (double)v) * 3.14159265358979323846 / 180.0;
        double c = cos(a), s = sin(a);
        double X = ((w + 0.5) * 2.0) / 32.0 - 1.0;
        double Y = ((h + 0.5) * 2.0) / 32.0 - 1.0;
        double gx = c * X - s * Y;
        double gy = s * X + c * Y;
        float ix = (float)((gx + 1.0) * 32.0 / 2.0 - 0.5);
        float iy = (float)((gy + 1.0) * 32.0 / 2.0 - 0.5);

        float x0f = floorf(ix), y0f = floorf(iy);
        float wx1 = ix - x0f, wy1 = iy - y0f;
        float wx0 = 1.0f - wx1, wy0 = 1.0f - wy1;
        int x0 = (int)x0f, y0 = (int)y0f;
        int x1 = x0 + 1, y1 = y0 + 1;

        auto ok = [](int yy, int xx) { return yy >= 0 && yy < H_ && xx >= 0 && xx < W_; };
        float w00 = ok(y0, x0) ? wy0 * wx0 : 0.0f;
        float w01 = ok(y0, x1) ? wy0 * wx1 : 0.0f;
        float w10 = ok(y1, x0) ? wy1 * wx0 : 0.0f;
        float w11 = ok(y1, x1) ? wy1 * wx1 : 0.0f;

        auto cl = [](int v_, int hi) { return v_ < 0 ? 0 : (v_ > hi ? hi : v_); };
        int y0c = cl(y0, H_ - 1), y1c = cl(y1, H_ - 1);
        int x0c = cl(x0, W_ - 1), x1c = cl(x1, W_ - 1);
        // padded smem row stride 33
        short i00 = (short)(y0c * 33 + x0c);
        short i01 = (short)(y0c * 33 + x1c);
        short i10 = (short)(y1c * 33 + x0c);
        short i11 = (short)(y1c * 33 + x1c);

        g_wtab[gid] = make_float4(w00, w01, w10, w11);
        g_itab[gid] = make_short4(i00, i01, i10, i11);
    }
}

// ---------------------------------------------------------------------------
// Kernel 1: group norm  (grid = B*GROUPS = 16 blocks, 256 threads)
// ---------------------------------------------------------------------------
__global__ void k_gn(const float* __restrict__ u,
                     const float* __restrict__ gw,
                     const float* __restrict__ gb) {
    int b = blockIdx.x >> 2;
    int g = blockIdx.x & 3;
    const float* base = u + ((size_t)(b * D_ + g * 16) << 10);

    float s = 0.f, ss = 0.f;
    for (int i = threadIdx.x; i < 16 * HW; i += 256) {
        float x = base[i];
        s += x;
        ss = fmaf(x, x, ss);
    }
    // warp reduce
    for (int o = 16; o; o >>= 1) {
        s  += __shfl_down_sync(0xffffffffu, s, o);
        ss += __shfl_down_sync(0xffffffffu, ss, o);
    }
    __shared__ float shs[8], shss[8];
    int wid = threadIdx.x >> 5, lid = threadIdx.x & 31;
    if (lid == 0) { shs[wid] = s; shss[wid] = ss; }
    __syncthreads();
    if (threadIdx.x == 0) {
        float S = 0.f, SS = 0.f;
        for (int i = 0; i < 8; i++) { S += shs[i]; SS += shss[i]; }
        float mu  = S / 16384.0f;
        float var = SS / 16384.0f - mu * mu;
        shs[0]  = mu;
        shss[0] = rsqrtf(var + EPS);
    }
    __syncthreads();
    float mu = shs[0], sc = shss[0];

    float* dst = g_unorm + ((size_t)(b * D_ + g * 16) << 10);
    for (int i = threadIdx.x; i < 16 * HW; i += 256) {
        int ch = g * 16 + (i >> 10);
        dst[i] = (base[i] - mu) * sc * gw[ch] + gb[ch];
    }
}

// ---------------------------------------------------------------------------
// Kernel 2: fused 3x3 convs (delta 64ch + B 16ch + C 16ch = 96 "oc")
// grid = B * 48 (2 oc per block), 256 threads, 4 consecutive pixels/thread
// ---------------------------------------------------------------------------
__global__ __launch_bounds__(256)
void k_conv(const float* __restrict__ wD, const float* __restrict__ bD,
            const float* __restrict__ wB, const float* __restrict__ wC,
            const float* __restrict__ u_t, const float* __restrict__ dt_bias_p) {
    int ocp = blockIdx.x % 48;
    int b   = blockIdx.x / 48;

    __shared__ float wsh[2 * D_ * 9];     // 4608 B
    __shared__ float plane[34 * 34];      // 4624 B (zero-padded halo)

    // load weights for the two output channels
    for (int k = threadIdx.x; k < 2 * D_ * 9; k += 256) {
        int j  = k / (D_ * 9);
        int kk = k - j * (D_ * 9);
        int oc = ocp * 2 + j;
        const float* src;
        if (oc < 64)      src = wD + (size_t)oc * 576;
        else if (oc < 80) src = wB + (size_t)(oc - 64) * 576;
        else              src = wC + (size_t)(oc - 80) * 576;
        wsh[k] = src[kk];
    }
    // zero halo (interior overwritten each iteration)
    for (int k = threadIdx.x; k < 34 * 34; k += 256) plane[k] = 0.0f;

    int p0 = threadIdx.x * 4;
    int h  = p0 >> 5;
    int w0 = p0 & 31;

    float acc0[4] = {0.f, 0.f, 0.f, 0.f};
    float acc1[4] = {0.f, 0.f, 0.f, 0.f};

    for (int ic = 0; ic < D_; ic++) {
        __syncthreads();
        const float* up = g_unorm + ((size_t)(b * D_ + ic) << 10);
        for (int k = threadIdx.x; k < HW; k += 256) {
            plane[((k >> 5) + 1) * 34 + (k & 31) + 1] = up[k];
        }
        __syncthreads();

        // 3x6 window (rows h..h+2, cols w0..w0+5 in padded coords)
        float win[3][6];
#pragma unroll
        for (int r = 0; r < 3; r++)
#pragma unroll
            for (int c = 0; c < 6; c++)
                win[r][c] = plane[(h + r) * 34 + w0 + c];

        const float* w0p = &wsh[0 * D_ * 9 + ic * 9];
        const float* w1p = &wsh[1 * D_ * 9 + ic * 9];
#pragma unroll
        for (int r = 0; r < 3; r++) {
#pragma unroll
            for (int c = 0; c < 3; c++) {
                float f0 = w0p[r * 3 + c];
                float f1 = w1p[r * 3 + c];
#pragma unroll
                for (int px = 0; px < 4; px++) {
                    float t = win[r][px + c];
                    acc0[px] = fmaf(t, f0, acc0[px]);
                    acc1[px] = fmaf(t, f1, acc1[px]);
                }
            }
        }
    }

    float dtb = dt_bias_p[0];

#pragma unroll
    for (int j = 0; j < 2; j++) {
        float* acc = j ? acc1 : acc0;
        int oc = ocp * 2 + j;
        if (oc < 64) {
            float bias = bD[oc] + dtb;
            float4 dlt, duv;
            const float* up = u_t + ((size_t)(b * D_ + oc) << 10) + p0;
            float* dv = (float*)&dlt;
            float* uv = (float*)&duv;
#pragma unroll
            for (int px = 0; px < 4; px++) {
                float x  = acc[px] + bias;
                float sp = fmaxf(x, 0.0f) + log1pf(expf(-fabsf(x)));
                float d  = fminf(fmaxf(sp, 1e-4f), 5.0f);
                dv[px] = d;
                uv[px] = d * up[px];
            }
            size_t idx = ((size_t)(b * D_ + oc) << 10) + p0;
            *(float4*)&g_delta[idx] = dlt;
            *(float4*)&g_du[idx]    = duv;
        } else {
            float4 o = make_float4(acc[0], acc[1], acc[2], acc[3]);
            if (oc < 80) {
                size_t idx = ((size_t)(b * N_ + (oc - 64)) << 10) + p0;
                *(float4*)&g_Bv[idx] = o;
            } else {
                size_t idx = ((size_t)(b * N_ + (oc - 80)) << 10) + p0;
                *(float4*)&g_Cv[idx] = o;
            }
        }
    }
}

// ---------------------------------------------------------------------------
// Kernel 3: main transport + SSM update + einsum
// grid = B*V*D = 2048 blocks, 1024 threads (1 pixel/thread)
// smem: 8 planes of 33*32 (stride-33 padding), 2 phases over n
// ---------------------------------------------------------------------------
__global__ __launch_bounds__(1024)
void k_main(const float* __restrict__ s_prev,
            const float* __restrict__ u_t,
            const float* __restrict__ Dp,
            float* __restrict__ y_out,
            float* __restrict__ s_out) {
    int blk = blockIdx.x;                 // = ((b*V + v)*D + d)
    int d = blk & 63;
    int v = (blk >> 6) & 7;
    int b = blk >> 9;

    __shared__ float sp[8 * 1056];        // 33792 B
    __shared__ float Ash[N_];

    int tid = threadIdx.x;
    if (tid < N_) Ash[tid] = g_A[d * N_ + tid];

    int p = tid;
    int tabi = (v << 10) + p;
    float4 wt = g_wtab[tabi];
    short4 it = g_itab[tabi];

    int bd = b * D_ + d;
    float delta_p = g_delta[((size_t)bd << 10) + p];
    float du_p    = g_du   [((size_t)bd << 10) + p];
    float u_p     = u_t    [((size_t)bd << 10) + p];

    const float* sbase     = s_prev + ((size_t)blk << 14);   // 16 contiguous planes
    float*       snew_base = s_out  + ((size_t)blk << 14);
    const float* Bvb = g_Bv + ((size_t)b << 14) + p;
    const float* Cvb = g_Cv + ((size_t)b << 14) + p;

    float yacc = 0.0f;

#pragma unroll
    for (int half = 0; half < 2; half++) {
        __syncthreads();
        // stage 8 planes (8192 floats) into padded smem
        const float4* src = (const float4*)(sbase + half * 8192);
#pragma unroll
        for (int k = tid; k < 2048; k += 1024) {
            float4 vls = src[k];
            int l  = k << 2;
            int n  = l >> 10;
            int pp = l & 1023;
            float* dst = &sp[n * 1056 + (pp >> 5) * 33 + (pp & 31)];
            dst[0] = vls.x; dst[1] = vls.y; dst[2] = vls.z; dst[3] = vls.w;
        }
        __syncthreads();

#pragma unroll
        for (int nn = 0; nn < 8; nn++) {
            int n = half * 8 + nn;
            const float* pl = &sp[nn * 1056];
            float st = wt.x * pl[it.x] + wt.y * pl[it.y]
                     + wt.z * pl[it.z] + wt.w * pl[it.w];
            float abar = __expf(delta_p * Ash[n]);
            float bv   = Bvb[(size_t)n << 10];
            float snew = fmaf(abar, st, du_p * bv);
            snew_base[((size_t)n << 10) + p] = snew;
            yacc = fmaf(snew, Cvb[(size_t)n << 10], yacc);
        }
    }

    y_out[((size_t)blk << 10) + p] = yacc + u_p * Dp[d];
}

// ---------------------------------------------------------------------------
// Launch
// ---------------------------------------------------------------------------
extern "C" void kernel_launch(void* const* d_in, const int* in_sizes, int n_in,
                              void* d_out, int out_size) {
    const float* u_t      = (const float*)d_in[0];
    const float* s_prev   = (const float*)d_in[1];
    const float* gn_w     = (const float*)d_in[2];
    const float* gn_b     = (const float*)d_in[3];
    const float* cdw      = (const float*)d_in[4];
    const float* cdb      = (const float*)d_in[5];
    const float* cBw      = (const float*)d_in[6];
    const float* cCw      = (const float*)d_in[7];
    const float* logA     = (const float*)d_in[8];
    const float* D_param  = (const float*)d_in[9];
    const float* dt_bias  = (const float*)d_in[10];

    float* y_out = (float*)d_out;                              // (B,V,D,H,W)
    float* s_out = (float*)d_out + (size_t)B_ * V_ * D_ * HW;  // (B,V,D,N,H,W)

    k_init<<<32, 256>>>(logA);
    k_gn<<<B_ * GROUPS, 256>>>(u_t, gn_w, gn_b);
    k_conv<<<B_ * 48, 256>>>(cdw, cdb, cBw, cCw, u_t, dt_bias);
    k_main<<<B_ * V_ * D_, 1024>>>(s_prev, u_t, D_param, y_out, s_out);
}

// round 5
// speedup vs baseline: 1.4680x; 1.4680x over previous
#include <cuda_runtime.h>
#include <math.h>

// ---------------------------------------------------------------------------
// Problem constants
// ---------------------------------------------------------------------------
#define B_ 4
#define V_ 8
#define D_ 64
#define N_ 16
#define H_ 32
#define W_ 32
#define HW 1024
#define EPS 1e-5f

// ---------------------------------------------------------------------------
// Scratch (device globals; no dynamic allocation allowed)
// ---------------------------------------------------------------------------
__device__ float  g_delta[B_ * D_ * HW];   // clipped softplus delta
__device__ float  g_du   [B_ * D_ * HW];   // delta * u_t
__device__ float  g_Bv   [B_ * N_ * HW];   // conv_B(u_norm)
__device__ float  g_Cv   [B_ * N_ * HW];   // conv_C(u_norm)
__device__ float  g_A    [D_ * N_];        // -exp(log_A_real)
__device__ float2 g_stat [B_ * 4];         // per (b, group): (mu, rsqrt(var+eps))
__device__ float4 g_wtab [V_ * HW];        // bilinear weights (masked)
__device__ short4 g_itab [V_ * HW];        // padded-smem tap offsets (stride 33)

// ---------------------------------------------------------------------------
// Kernel 0: fused GN-stats (blocks 0..15) + init tables (blocks 16..47)
// ---------------------------------------------------------------------------
__global__ __launch_bounds__(256)
void k_stats_init(const float* __restrict__ u, const float* __restrict__ log_A_real) {
    int blk = blockIdx.x;
    int tid = threadIdx.x;

    if (blk < 16) {
        // blk = b*4 + g ; reduce 16 channel planes = 16384 floats
        const float4* base = (const float4*)(u + ((size_t)blk << 14));
        float s = 0.f, ss = 0.f;
        for (int i = tid; i < 4096; i += 256) {
            float4 v = base[i];
            s += v.x + v.y + v.z + v.w;
            ss = fmaf(v.x, v.x, ss);
            ss = fmaf(v.y, v.y, ss);
            ss = fmaf(v.z, v.z, ss);
            ss = fmaf(v.w, v.w, ss);
        }
        for (int o = 16; o; o >>= 1) {
            s  += __shfl_down_sync(0xffffffffu, s, o);
            ss += __shfl_down_sync(0xffffffffu, ss, o);
        }
        __shared__ float shs[8], shss[8];
        int wid = tid >> 5, lid = tid & 31;
        if (lid == 0) { shs[wid] = s; shss[wid] = ss; }
        __syncthreads();
        if (tid == 0) {
            float S = 0.f, SS = 0.f;
            for (int i = 0; i < 8; i++) { S += shs[i]; SS += shss[i]; }
            float mu  = S / 16384.0f;
            float var = SS / 16384.0f - mu * mu;
            g_stat[blk] = make_float2(mu, rsqrtf(var + EPS));
        }
        return;
    }

    int gid = (blk - 16) * 256 + tid;      // 0..8191
    if (gid < D_ * N_) {
        g_A[gid] = -expf(log_A_real[gid]);
    }
    {
        int v = gid >> 10;
        int p = gid & 1023;
        int h = p >> 5, w = p & 31;
        double a = -(45.0 * (double)v) * 3.14159265358979323846 / 180.0;
        double c = cos(a), sn = sin(a);
        double X = ((w + 0.5) * 2.0) / 32.0 - 1.0;
        double Y = ((h + 0.5) * 2.0) / 32.0 - 1.0;
        double gx = c * X - sn * Y;
        double gy = sn * X + c * Y;
        float ix = (float)((gx + 1.0) * 32.0 / 2.0 - 0.5);
        float iy = (float)((gy + 1.0) * 32.0 / 2.0 - 0.5);

        float x0f = floorf(ix), y0f = floorf(iy);
        float wx1 = ix - x0f, wy1 = iy - y0f;
        float wx0 = 1.0f - wx1, wy0 = 1.0f - wy1;
        int x0 = (int)x0f, y0 = (int)y0f;
        int x1 = x0 + 1, y1 = y0 + 1;

        auto ok = [](int yy, int xx) { return yy >= 0 && yy < H_ && xx >= 0 && xx < W_; };
        float w00 = ok(y0, x0) ? wy0 * wx0 : 0.0f;
        float w01 = ok(y0, x1) ? wy0 * wx1 : 0.0f;
        float w10 = ok(y1, x0) ? wy1 * wx0 : 0.0f;
        float w11 = ok(y1, x1) ? wy1 * wx1 : 0.0f;

        auto cl = [](int v_, int hi) { return v_ < 0 ? 0 : (v_ > hi ? hi : v_); };
        int y0c = cl(y0, H_ - 1), y1c = cl(y1, H_ - 1);
        int x0c = cl(x0, W_ - 1), x1c = cl(x1, W_ - 1);
        short i00 = (short)(y0c * 33 + x0c);
        short i01 = (short)(y0c * 33 + x1c);
        short i10 = (short)(y1c * 33 + x0c);
        short i11 = (short)(y1c * 33 + x1c);

        g_wtab[gid] = make_float4(w00, w01, w10, w11);
        g_itab[gid] = make_short4(i00, i01, i10, i11);
    }
}

// ---------------------------------------------------------------------------
// Kernel 1: fused 3x3 convs + inline group-norm of input planes
// grid = B * 24 oc-quads * 4 row-strips = 384 blocks, 256 threads, 1 px/thread
//   oc-quad j=0..3 -> oc = ocq*4+j ; oc<64: delta, 64..79: B, 80..95: C
// ---------------------------------------------------------------------------
__global__ __launch_bounds__(256)
void k_conv(const float* __restrict__ wD, const float* __restrict__ bD,
            const float* __restrict__ wB, const float* __restrict__ wC,
            const float* __restrict__ u_t,
            const float* __restrict__ gw, const float* __restrict__ gb,
            const float* __restrict__ dt_bias_p) {
    int strip = blockIdx.x & 3;
    int rest  = blockIdx.x >> 2;
    int ocq   = rest % 24;
    int b     = rest / 24;

    __shared__ float wsh[4 * D_ * 9];   // 9216 B
    __shared__ float pl[10 * 34];       // 1360 B (8-row strip + halo)

    // load weights for the 4 output channels
    for (int k = threadIdx.x; k < 4 * D_ * 9; k += 256) {
        int j  = k / (D_ * 9);
        int kk = k - j * (D_ * 9);
        int oc = ocq * 4 + j;
        const float* src;
        if (oc < 64)      src = wD + (size_t)oc * 576;
        else if (oc < 80) src = wB + (size_t)(oc - 64) * 576;
        else              src = wC + (size_t)(oc - 80) * 576;
        wsh[k] = src[kk];
    }

    int h0    = strip * 8;
    int local = threadIdx.x >> 5;   // 0..7  (row within strip)
    int col   = threadIdx.x & 31;

    float acc[4] = {0.f, 0.f, 0.f, 0.f};

    for (int ic = 0; ic < D_; ic++) {
        __syncthreads();
        float2 st   = g_stat[b * 4 + (ic >> 4)];
        float scale = st.y * gw[ic];
        float shift = gb[ic] - st.x * scale;
        const float* up = u_t + ((size_t)(b * D_ + ic) << 10);
        for (int k = threadIdx.x; k < 340; k += 256) {
            int r  = k / 34;
            int c  = k - r * 34;
            int gr = h0 - 1 + r;
            int gc = c - 1;
            float vv = 0.0f;
            if (gr >= 0 && gr < 32 && gc >= 0 && gc < 32)
                vv = fmaf(up[gr * 32 + gc], scale, shift);
            pl[k] = vv;
        }
        __syncthreads();

        const float* wp = &wsh[ic * 9];
#pragma unroll
        for (int r = 0; r < 3; r++) {
#pragma unroll
            for (int c = 0; c < 3; c++) {
                float t = pl[(local + r) * 34 + col + c];
#pragma unroll
                for (int j = 0; j < 4; j++)
                    acc[j] = fmaf(t, wp[j * D_ * 9 + r * 3 + c], acc[j]);
            }
        }
    }

    int p = (h0 + local) * 32 + col;
    if (ocq < 16) {
        float dtb = dt_bias_p[0];
#pragma unroll
        for (int j = 0; j < 4; j++) {
            int oc = ocq * 4 + j;
            float x  = acc[j] + bD[oc] + dtb;
            float sp = fmaxf(x, 0.0f) + log1pf(expf(-fabsf(x)));
            float d  = fminf(fmaxf(sp, 1e-4f), 5.0f);
            size_t idx = ((size_t)(b * D_ + oc) << 10) + p;
            g_delta[idx] = d;
            g_du[idx]    = d * u_t[idx];
        }
    } else if (ocq < 20) {
#pragma unroll
        for (int j = 0; j < 4; j++) {
            int n = (ocq - 16) * 4 + j;
            g_Bv[((size_t)(b * N_ + n) << 10) + p] = acc[j];
        }
    } else {
#pragma unroll
        for (int j = 0; j < 4; j++) {
            int n = (ocq - 20) * 4 + j;
            g_Cv[((size_t)(b * N_ + n) << 10) + p] = acc[j];
        }
    }
}

// ---------------------------------------------------------------------------
// Kernel 2: main transport + SSM update + einsum
// grid = B*V*D = 2048 blocks, 256 threads (4 consecutive pixels/thread)
// 4 phases of 4 planes; stride-33 padded smem; single-tap fast path for
// exact rotations (0/90/180/270 deg); streaming loads/stores for s traffic.
// ---------------------------------------------------------------------------
__global__ __launch_bounds__(256)
void k_main(const float* __restrict__ s_prev,
            const float* __restrict__ u_t,
            const float* __restrict__ Dp,
            float* __restrict__ y_out,
            float* __restrict__ s_out) {
    int blk = blockIdx.x;                 // = ((b*V + v)*D + d)
    int d = blk & 63;
    int v = (blk >> 6) & 7;
    int b = blk >> 9;

    __shared__ float sp[4 * 1056];        // 16896 B
    __shared__ float Ash[N_];

    int tid = threadIdx.x;
    if (tid < N_) Ash[tid] = g_A[d * N_ + tid];

    int p0 = tid * 4;

    float4 wt[4];
    short4 it[4];
    bool   single[4];
#pragma unroll
    for (int i = 0; i < 4; i++) {
        int tabi = (v << 10) + p0 + i;
        wt[i] = g_wtab[tabi];
        it[i] = g_itab[tabi];
        single[i] = (wt[i].y == 0.0f) && (wt[i].z == 0.0f) && (wt[i].w == 0.0f);
    }

    size_t bdp = ((size_t)(b * D_ + d) << 10) + p0;
    float4 dl4 = *(const float4*)&g_delta[bdp];
    float4 du4 = *(const float4*)&g_du[bdp];
    float4 u4  = *(const float4*)&u_t[bdp];
    float dl[4] = {dl4.x, dl4.y, dl4.z, dl4.w};
    float du[4] = {du4.x, du4.y, du4.z, du4.w};

    const float* sbase = s_prev + ((size_t)blk << 14);
    float*       snb   = s_out  + ((size_t)blk << 14);
    const float* Bvb   = g_Bv + ((size_t)b << 14) + p0;
    const float* Cvb   = g_Cv + ((size_t)b << 14) + p0;

    float yacc[4] = {0.f, 0.f, 0.f, 0.f};

#pragma unroll
    for (int ph = 0; ph < 4; ph++) {
        __syncthreads();
        const float4* src = (const float4*)(sbase + ph * 4096);
#pragma unroll
        for (int k = tid; k < 1024; k += 256) {
            float4 vv = __ldcs(&src[k]);
            int l  = k << 2;
            int n  = l >> 10;
            int pp = l & 1023;
            float* dst = &sp[n * 1056 + (pp >> 5) * 33 + (pp & 31)];
            dst[0] = vv.x; dst[1] = vv.y; dst[2] = vv.z; dst[3] = vv.w;
        }
        __syncthreads();

#pragma unroll
        for (int nn = 0; nn < 4; nn++) {
            int n = ph * 4 + nn;
            const float* pl = &sp[nn * 1056];
            float A_n = Ash[n];
            float4 bv = *(const float4*)&Bvb[(size_t)n << 10];
            float4 cv = *(const float4*)&Cvb[(size_t)n << 10];
            float bva[4] = {bv.x, bv.y, bv.z, bv.w};
            float cva[4] = {cv.x, cv.y, cv.z, cv.w};
            float sn[4];
#pragma unroll
            for (int i = 0; i < 4; i++) {
                float st;
                if (single[i]) {
                    st = wt[i].x * pl[it[i].x];
                } else {
                    st = wt[i].x * pl[it[i].x] + wt[i].y * pl[it[i].y]
                       + wt[i].z * pl[it[i].z] + wt[i].w * pl[it[i].w];
                }
                float ab = __expf(dl[i] * A_n);
                sn[i] = fmaf(ab, st, du[i] * bva[i]);
                yacc[i] = fmaf(sn[i], cva[i], yacc[i]);
            }
            float4 so = make_float4(sn[0], sn[1], sn[2], sn[3]);
            __stcs((float4*)&snb[((size_t)n << 10) + p0], so);
        }
    }

    float Dd = Dp[d];
    float4 yo = make_float4(fmaf(u4.x, Dd, yacc[0]),
                            fmaf(u4.y, Dd, yacc[1]),
                            fmaf(u4.z, Dd, yacc[2]),
                            fmaf(u4.w, Dd, yacc[3]));
    *(float4*)&y_out[((size_t)blk << 10) + p0] = yo;
}

// ---------------------------------------------------------------------------
// Launch
// ---------------------------------------------------------------------------
extern "C" void kernel_launch(void* const* d_in, const int* in_sizes, int n_in,
                              void* d_out, int out_size) {
    const float* u_t      = (const float*)d_in[0];
    const float* s_prev   = (const float*)d_in[1];
    const float* gn_w     = (const float*)d_in[2];
    const float* gn_b     = (const float*)d_in[3];
    const float* cdw      = (const float*)d_in[4];
    const float* cdb      = (const float*)d_in[5];
    const float* cBw      = (const float*)d_in[6];
    const float* cCw      = (const float*)d_in[7];
    const float* logA     = (const float*)d_in[8];
    const float* D_param  = (const float*)d_in[9];
    const float* dt_bias  = (const float*)d_in[10];

    float* y_out = (float*)d_out;                              // (B,V,D,H,W)
    float* s_out = (float*)d_out + (size_t)B_ * V_ * D_ * HW;  // (B,V,D,N,H,W)

    k_stats_init<<<48, 256>>>(u_t, logA);
    k_conv<<<B_ * 24 * 4, 256>>>(cdw, cdb, cBw, cCw, u_t, gn_w, gn_b, dt_bias);
    k_main<<<B_ * V_ * D_, 256>>>(s_prev, u_t, D_param, y_out, s_out);
}

// round 7
// speedup vs baseline: 1.8871x; 1.2855x over previous
#include <cuda_runtime.h>
#include <math.h>

// ---------------------------------------------------------------------------
// Problem constants
// ---------------------------------------------------------------------------
#define B_ 4
#define V_ 8
#define D_ 64
#define N_ 16
#define H_ 32
#define W_ 32
#define HW 1024
#define EPS 1e-5f

// ---------------------------------------------------------------------------
// Scratch (device globals; no dynamic allocation allowed)
// ---------------------------------------------------------------------------
__device__ float  g_delta[B_ * D_ * HW];   // clipped softplus delta
__device__ float  g_du   [B_ * D_ * HW];   // delta * u_t
__device__ float  g_Bv   [B_ * N_ * HW];   // conv_B(u_norm)
__device__ float  g_Cv   [B_ * N_ * HW];   // conv_C(u_norm)
__device__ float  g_A    [D_ * N_];        // -exp(log_A_real)
__device__ float2 g_stat [B_ * 4];         // per (b, group): (mu, rsqrt(var+eps))
__device__ float4 g_wtab [V_ * HW];        // bilinear weights (masked)
__device__ short4 g_itab [V_ * HW];        // padded-smem tap offsets (stride 33)

// ---------------------------------------------------------------------------
// Kernel 0: fused GN-stats (blocks 0..15) + init tables (blocks 16..47)
// Double trig computed ONCE per block (thread 0), broadcast via smem.
// ---------------------------------------------------------------------------
__global__ __launch_bounds__(256)
void k_stats_init(const float* __restrict__ u, const float* __restrict__ log_A_real) {
    int blk = blockIdx.x;
    int tid = threadIdx.x;

    if (blk < 16) {
        // blk = b*4 + g ; reduce 16 channel planes = 16384 floats
        const float4* base = (const float4*)(u + ((size_t)blk << 14));
        float s = 0.f, ss = 0.f;
        for (int i = tid; i < 4096; i += 256) {
            float4 v = base[i];
            s += v.x + v.y + v.z + v.w;
            ss = fmaf(v.x, v.x, ss);
            ss = fmaf(v.y, v.y, ss);
            ss = fmaf(v.z, v.z, ss);
            ss = fmaf(v.w, v.w, ss);
        }
        for (int o = 16; o; o >>= 1) {
            s  += __shfl_down_sync(0xffffffffu, s, o);
            ss += __shfl_down_sync(0xffffffffu, ss, o);
        }
        __shared__ float shs[8], shss[8];
        int wid = tid >> 5, lid = tid & 31;
        if (lid == 0) { shs[wid] = s; shss[wid] = ss; }
        __syncthreads();
        if (tid == 0) {
            float S = 0.f, SS = 0.f;
            for (int i = 0; i < 8; i++) { S += shs[i]; SS += shss[i]; }
            float mu  = S / 16384.0f;
            float var = SS / 16384.0f - mu * mu;
            g_stat[blk] = make_float2(mu, rsqrtf(var + EPS));
        }
        return;
    }

    int gid = (blk - 16) * 256 + tid;      // 0..8191 ; one v per block
    if (gid < D_ * N_) {
        g_A[gid] = -expf(log_A_real[gid]);
    }

    __shared__ double sh_c, sh_s;
    int v = gid >> 10;
    if (tid == 0) {
        double a = -(45.0 * (double)v) * 3.14159265358979323846 / 180.0;
        sh_c = cos(a);
        sh_s = sin(a);
    }
    __syncthreads();
    double c = sh_c, sn = sh_s;

    {
        int p = gid & 1023;
        int h = p >> 5, w = p & 31;
        double X = ((w + 0.5) * 2.0) / 32.0 - 1.0;
        double Y = ((h + 0.5) * 2.0) / 32.0 - 1.0;
        double gx = c * X - sn * Y;
        double gy = sn * X + c * Y;
        float ix = (float)((gx + 1.0) * 32.0 / 2.0 - 0.5);
        float iy = (float)((gy + 1.0) * 32.0 / 2.0 - 0.5);

        float x0f = floorf(ix), y0f = floorf(iy);
        float wx1 = ix - x0f, wy1 = iy - y0f;
        float wx0 = 1.0f - wx1, wy0 = 1.0f - wy1;
        int x0 = (int)x0f, y0 = (int)y0f;
        int x1 = x0 + 1, y1 = y0 + 1;

        auto ok = [](int yy, int xx) { return yy >= 0 && yy < H_ && xx >= 0 && xx < W_; };
        float w00 = ok(y0, x0) ? wy0 * wx0 : 0.0f;
        float w01 = ok(y0, x1) ? wy0 * wx1 : 0.0f;
        float w10 = ok(y1, x0) ? wy1 * wx0 : 0.0f;
        float w11 = ok(y1, x1) ? wy1 * wx1 : 0.0f;

        auto cl = [](int v_, int hi) { return v_ < 0 ? 0 : (v_ > hi ? hi : v_); };
        int y0c = cl(y0, H_ - 1), y1c = cl(y1, H_ - 1);
        int x0c = cl(x0, W_ - 1), x1c = cl(x1, W_ - 1);
        short i00 = (short)(y0c * 33 + x0c);
        short i01 = (short)(y0c * 33 + x1c);
        short i10 = (short)(y1c * 33 + x0c);
        short i11 = (short)(y1c * 33 + x1c);

        g_wtab[gid] = make_float4(w00, w01, w10, w11);
        g_itab[gid] = make_short4(i00, i01, i10, i11);
    }
}

// ---------------------------------------------------------------------------
// Kernel 1: fused 3x3 convs + inline group-norm, software-pipelined staging
// grid = B * 24 oc-quads * 4 row-strips = 384 blocks, 256 threads
// 2 ic per round, double-buffered smem, register prefetch, 1 sync/round.
// ---------------------------------------------------------------------------
__global__ __launch_bounds__(256)
void k_conv(const float* __restrict__ wD, const float* __restrict__ bD,
            const float* __restrict__ wB, const float* __restrict__ wC,
            const float* __restrict__ u_t,
            const float* __restrict__ gw, const float* __restrict__ gb,
            const float* __restrict__ dt_bias_p) {
    int strip = blockIdx.x & 3;
    int rest  = blockIdx.x >> 2;
    int ocq   = rest % 24;
    int b     = rest / 24;
    int tid   = threadIdx.x;

    __shared__ float wsh[4 * D_ * 9];    // 9216 B
    __shared__ float buf[2][2][340];     // 5440 B : [dbuf][ic-in-pair][elem]
    __shared__ float ssc[64], ssh[64];   // per-ic normalize scale/shift

    // load weights for the 4 output channels
    for (int k = tid; k < 4 * D_ * 9; k += 256) {
        int j  = k / (D_ * 9);
        int kk = k - j * (D_ * 9);
        int oc = ocq * 4 + j;
        const float* src;
        if (oc < 64)      src = wD + (size_t)oc * 576;
        else if (oc < 80) src = wB + (size_t)(oc - 64) * 576;
        else              src = wC + (size_t)(oc - 80) * 576;
        wsh[k] = src[kk];
    }
    if (tid < 64) {
        float2 st = g_stat[b * 4 + (tid >> 4)];
        float sc = st.y * gw[tid];
        ssc[tid] = sc;
        ssh[tid] = gb[tid] - st.x * sc;
    }

    int h0    = strip * 8;
    int local = tid >> 5;    // 0..7
    int col   = tid & 31;

    // hoisted staging index math (pattern identical across ic)
    int r1 = tid / 34, c1 = tid - r1 * 34;
    int gr1 = h0 - 1 + r1, gc1 = c1 - 1;
    bool ok1 = (gr1 >= 0) && (gr1 < 32) && (gc1 >= 0) && (gc1 < 32);
    int go1 = ok1 ? gr1 * 32 + gc1 : 0;
    int k2 = tid + 256;
    bool has2 = (k2 < 340);
    int r2 = k2 / 34, c2 = k2 - r2 * 34;
    int gr2 = h0 - 1 + r2, gc2 = c2 - 1;
    bool ok2 = has2 && (gr2 >= 0) && (gr2 < 32) && (gc2 >= 0) && (gc2 < 32);
    int go2 = ok2 ? gr2 * 32 + gc2 : 0;

    const float* ubase = u_t + ((size_t)b << 16);   // b * 64 * 1024

    float acc[4] = {0.f, 0.f, 0.f, 0.f};

    // prologue: raw loads for pair 0 (ic 0,1)
    float ra0 = ok1 ? __ldg(ubase + go1)        : 0.f;
    float ra1 = ok1 ? __ldg(ubase + 1024 + go1) : 0.f;
    float rb0 = ok2 ? __ldg(ubase + go2)        : 0.f;
    float rb1 = ok2 ? __ldg(ubase + 1024 + go2) : 0.f;
    __syncthreads();   // weights + ssc/ssh visible

    buf[0][0][tid] = ok1 ? fmaf(ra0, ssc[0], ssh[0]) : 0.f;
    buf[0][1][tid] = ok1 ? fmaf(ra1, ssc[1], ssh[1]) : 0.f;
    if (has2) {
        buf[0][0][k2] = ok2 ? fmaf(rb0, ssc[0], ssh[0]) : 0.f;
        buf[0][1][k2] = ok2 ? fmaf(rb1, ssc[1], ssh[1]) : 0.f;
    }
    __syncthreads();

    for (int pair = 0; pair < 32; pair++) {
        int cur = pair & 1;
        int nxt = cur ^ 1;
        int icn0 = pair * 2 + 2;

        // prefetch next pair
        if (pair < 31) {
            const float* u0 = ubase + ((size_t)icn0 << 10);
            ra0 = ok1 ? __ldg(u0 + go1)        : 0.f;
            ra1 = ok1 ? __ldg(u0 + 1024 + go1) : 0.f;
            rb0 = ok2 ? __ldg(u0 + go2)        : 0.f;
            rb1 = ok2 ? __ldg(u0 + 1024 + go2) : 0.f;
        }

        // compute current pair
#pragma unroll
        for (int ii = 0; ii < 2; ii++) {
            int ic = pair * 2 + ii;
            const float* pb = buf[cur][ii];
            const float* wp = &wsh[ic * 9];
#pragma unroll
            for (int r = 0; r < 3; r++) {
#pragma unroll
                for (int c = 0; c < 3; c++) {
                    float t = pb[(local + r) * 34 + col + c];
#pragma unroll
                    for (int j = 0; j < 4; j++)
                        acc[j] = fmaf(t, wp[j * D_ * 9 + r * 3 + c], acc[j]);
                }
            }
        }

        // store next pair
        if (pair < 31) {
            buf[nxt][0][tid] = ok1 ? fmaf(ra0, ssc[icn0],     ssh[icn0])     : 0.f;
            buf[nxt][1][tid] = ok1 ? fmaf(ra1, ssc[icn0 + 1], ssh[icn0 + 1]) : 0.f;
            if (has2) {
                buf[nxt][0][k2] = ok2 ? fmaf(rb0, ssc[icn0],     ssh[icn0])     : 0.f;
                buf[nxt][1][k2] = ok2 ? fmaf(rb1, ssc[icn0 + 1], ssh[icn0 + 1]) : 0.f;
            }
        }
        __syncthreads();
    }

    int p = (h0 + local) * 32 + col;
    if (ocq < 16) {
        float dtb = dt_bias_p[0];
#pragma unroll
        for (int j = 0; j < 4; j++) {
            int oc = ocq * 4 + j;
            float x  = acc[j] + bD[oc] + dtb;
            float sp = fmaxf(x, 0.0f) + log1pf(expf(-fabsf(x)));
            float d  = fminf(fmaxf(sp, 1e-4f), 5.0f);
            size_t idx = ((size_t)(b * D_ + oc) << 10) + p;
            g_delta[idx] = d;
            g_du[idx]    = d * u_t[idx];
        }
    } else if (ocq < 20) {
#pragma unroll
        for (int j = 0; j < 4; j++) {
            int n = (ocq - 16) * 4 + j;
            g_Bv[((size_t)(b * N_ + n) << 10) + p] = acc[j];
        }
    } else {
#pragma unroll
        for (int j = 0; j < 4; j++) {
            int n = (ocq - 20) * 4 + j;
            g_Cv[((size_t)(b * N_ + n) << 10) + p] = acc[j];
        }
    }
}

// ---------------------------------------------------------------------------
// Kernel 2: main transport + SSM update + einsum
// grid = B*V*D = 2048 blocks, 256 threads (4 consecutive pixels/thread)
//   v=0 : identity -> pure streaming, no smem/barriers
//   v=4 : 180 deg -> reversed float4 read, no smem/barriers
//   else: padded-smem gather, register-prefetched 4-plane phases
// ---------------------------------------------------------------------------
__global__ __launch_bounds__(256)
void k_main(const float* __restrict__ s_prev,
            const float* __restrict__ u_t,
            const float* __restrict__ Dp,
            float* __restrict__ y_out,
            float* __restrict__ s_out) {
    int blk = blockIdx.x;                 // = ((b*V + v)*D + d)
    int d = blk & 63;
    int v = (blk >> 6) & 7;
    int b = blk >> 9;

    __shared__ float sp[4 * 1056];        // 16896 B
    __shared__ float Ash[N_];

    int tid = threadIdx.x;
    int p0  = tid * 4;

    size_t bdp = ((size_t)(b * D_ + d) << 10) + p0;
    float4 dl4 = *(const float4*)&g_delta[bdp];
    float4 du4 = *(const float4*)&g_du[bdp];
    float4 u4  = *(const float4*)&u_t[bdp];
    float dl[4] = {dl4.x, dl4.y, dl4.z, dl4.w};
    float du[4] = {du4.x, du4.y, du4.z, du4.w};

    const float* sbase = s_prev + ((size_t)blk << 14);
    float*       snb   = s_out  + ((size_t)blk << 14);
    const float* Bvb   = g_Bv + ((size_t)b << 14) + p0;
    const float* Cvb   = g_Cv + ((size_t)b << 14) + p0;

    float yacc[4] = {0.f, 0.f, 0.f, 0.f};

    if (v == 0 || v == 4) {
        // exact permutations: identity (v=0) or point reflection (v=4)
        bool mir = (v == 4);
        int fidx = mir ? (255 - tid) : tid;        // float4 index within plane
#pragma
        for (int g = 0; g < 4; g++) {
            float4 sv[4];
#pragma unroll
            for (int j = 0; j < 4; j++)
                sv[j] = __ldcs((const float4*)(sbase + ((size_t)(g * 4 + j) << 10)) + fidx);
#pragma unroll
            for (int j = 0; j < 4; j++) {
                int n = g * 4 + j;
                float A_n = __ldg(&g_A[d * N_ + n]);
                float4 bv = *(const float4*)&Bvb[(size_t)n << 10];
                float4 cv = *(const float4*)&Cvb[(size_t)n << 10];
                float stv[4];
                if (mir) {
                    stv[0] = sv[j].w; stv[1] = sv[j].z; stv[2] = sv[j].y; stv[3] = sv[j].x;
                } else {
                    stv[0] = sv[j].x; stv[1] = sv[j].y; stv[2] = sv[j].z; stv[3] = sv[j].w;
                }
                float bva[4] = {bv.x, bv.y, bv.z, bv.w};
                float cva[4] = {cv.x, cv.y, cv.z, cv.w};
                float sn[4];
#pragma unroll
                for (int i = 0; i < 4; i++) {
                    float ab = __expf(dl[i] * A_n);
                    sn[i] = fmaf(ab, stv[i], du[i] * bva[i]);
                    yacc[i] = fmaf(sn[i], cva[i], yacc[i]);
                }
                float4 so = make_float4(sn[0], sn[1], sn[2], sn[3]);
                __stcs((float4*)&snb[((size_t)n << 10) + p0], so);
            }
        }
    } else {
        if (tid < N_) Ash[tid] = g_A[d * N_ + tid];

        float4 wt[4];
        short4 it[4];
        bool   single[4];
#pragma unroll
        for (int i = 0; i < 4; i++) {
            int tabi = (v << 10) + p0 + i;
            wt[i] = g_wtab[tabi];
            it[i] = g_itab[tabi];
            single[i] = (wt[i].y == 0.0f) && (wt[i].z == 0.0f) && (wt[i].w == 0.0f);
        }

        // prefetch phase 0 (pre[j] = plane j of the phase, float4 at 4*tid)
        float4 pre[4];
#pragma unroll
        for (int j = 0; j < 4; j++)
            pre[j] = __ldcs((const float4*)sbase + tid + j * 256);

        int pp  = p0;                    // = 4*tid, element offset within plane
        int soff = (pp >> 5) * 33 + (pp & 31);

#pragma unroll
        for (int ph = 0; ph < 4; ph++) {
            __syncthreads();             // prev compute done (also covers Ash on ph=0)
#pragma unroll
            for (int j = 0; j < 4; j++) {
                float* dst = &sp[j * 1056 + soff];
                dst[0] = pre[j].x; dst[1] = pre[j].y; dst[2] = pre[j].z; dst[3] = pre[j].w;
            }
            __syncthreads();             // staging visible

            if (ph < 3) {
                const float4* src = (const float4*)(sbase + (ph + 1) * 4096);
#pragma unroll
                for (int j = 0; j < 4; j++)
                    pre[j] = __ldcs(src + tid + j * 256);
            }

#pragma unroll
            for (int nn = 0; nn < 4; nn++) {
                int n = ph * 4 + nn;
                const float* pl = &sp[nn * 1056];
                float A_n = Ash[n];
                float4 bv = *(const float4*)&Bvb[(size_t)n << 10];
                float4 cv = *(const float4*)&Cvb[(size_t)n << 10];
                float bva[4] = {bv.x, bv.y, bv.z, bv.w};
                float cva[4] = {cv.x, cv.y, cv.z, cv.w};
                float sn[4];
#pragma unroll
                for (int i = 0; i < 4; i++) {
                    float st;
                    if (single[i]) {
                        st = wt[i].x * pl[it[i].x];
                    } else {
                        st = wt[i].x * pl[it[i].x] + wt[i].y * pl[it[i].y]
                           + wt[i].z * pl[it[i].z] + wt[i].w * pl[it[i].w];
                    }
                    float ab = __expf(dl[i] * A_n);
                    sn[i] = fmaf(ab, st, du[i] * bva[i]);
                    yacc[i] = fmaf(sn[i], cva[i], yacc[i]);
                }
                float4 so = make_float4(sn[0], sn[1], sn[2], sn[3]);
                __stcs((float4*)&snb[((size_t)n << 10) + p0], so);
            }
        }
    }

    float Dd = __ldg(&Dp[d]);
    float4 yo = make_float4(fmaf(u4.x, Dd, yacc[0]),
                            fmaf(u4.y, Dd, yacc[1]),
                            fmaf(u4.z, Dd, yacc[2]),
                            fmaf(u4.w, Dd, yacc[3]));
    *(float4*)&y_out[((size_t)blk << 10) + p0] = yo;
}

// ---------------------------------------------------------------------------
// Launch
// ---------------------------------------------------------------------------
extern "C" void kernel_launch(void* const* d_in, const int* in_sizes, int n_in,
                              void* d_out, int out_size) {
    const float* u_t      = (const float*)d_in[0];
    const float* s_prev   = (const float*)d_in[1];
    const float* gn_w     = (const float*)d_in[2];
    const float* gn_b     = (const float*)d_in[3];
    const float* cdw      = (const float*)d_in[4];
    const float* cdb      = (const float*)d_in[5];
    const float* cBw      = (const float*)d_in[6];
    const float* cCw      = (const float*)d_in[7];
    const float* logA     = (const float*)d_in[8];
    const float* D_param  = (const float*)d_in[9];
    const float* dt_bias  = (const float*)d_in[10];

    float* y_out = (float*)d_out;                              // (B,V,D,H,W)
    float* s_out = (float*)d_out + (size_t)B_ * V_ * D_ * HW;  // (B,V,D,N,H,W)

    k_stats_init<<<48, 256>>>(u_t, logA);
    k_conv<<<B_ * 24 * 4, 256>>>(cdw, cdb, cBw, cCw, u_t, gn_w, gn_b, dt_bias);
    k_main<<<B_ * V_ * D_, 256>>>(s_prev, u_t, D_param, y_out, s_out);
}